// round 4
// baseline (speedup 1.0000x reference)
#include <cuda_runtime.h>

// MultiScaleTrendDirectionLoss — fused EMA + sign-mismatch masked MSE.
// pred, target: [32, 8192, 64] fp32. Output: scalar fp32.
//
// R2: one thread per (b, chunk, d) scalar lane -> 2048 warps (~14/SM) to hide
// DRAM latency (R1 had 7 warps/SM and sat at ~3 TB/s). Reduction fused into
// the main kernel via last-block-done (R1's separate reduce kernel cost 6us).

#define Bn 32
#define Tn 8192
#define Dn 64
#define CHUNK 256
#define HALO 128
#define NCHUNK (Tn / CHUNK)        // 32
#define NROWS (Bn * NCHUNK)        // 1024
#define NWARPS (NROWS * 2)         // 2048: two warps per row (d 0-31, d 32-63)
#define TPB 256
#define WPB (TPB / 32)             // 8 warps per block
#define NBLK (NWARPS / WPB)        // 256 blocks

__device__ float g_partial[NWARPS];
__device__ unsigned int g_done = 0;

__global__ __launch_bounds__(TPB) void msl_fused(const float* __restrict__ pred,
                                                 const float* __restrict__ tgt,
                                                 float* __restrict__ out)
{
    const int lane = threadIdx.x & 31;
    const int wid  = threadIdx.x >> 5;
    const int gw   = blockIdx.x * WPB + wid;   // global warp id
    const int row  = gw >> 1;                  // (b, chunk)
    const int half = gw & 1;                   // which 32 d-lanes
    const int b  = row >> 5;
    const int c  = row & 31;
    const int cs = c * CHUNK;
    const int t0 = (c == 0) ? 0 : (cs - HALO);
    const int d  = half * 32 + lane;

    const float* __restrict__ pp = pred + ((size_t)(b * Tn + t0)) * Dn + d;
    const float* __restrict__ qq = tgt  + ((size_t)(b * Tn + t0)) * Dn + d;

    const float ALPHA[3] = {0.1f, 0.3f, 0.5f};

    // Seed EMA state with the element at t0 (exact for chunk 0; halo warm-up
    // otherwise — (0.9)^128 ~ 1.4e-6 residual, far below 1e-3 tolerance).
    float x0 = *pp;
    float y0 = *qq;
    float pe[3], te[3], acc[3];
#pragma unroll
    for (int k = 0; k < 3; ++k) { pe[k] = x0; te[k] = y0; acc[k] = 0.0f; }

    pp += Dn;
    qq += Dn;

    // Warm-up (no accumulation): 127 iters for c>0, none for c==0.
#pragma unroll 8
    for (int t = t0 + 1; t < cs; ++t, pp += Dn, qq += Dn) {
        float xv = *pp;
        float yv = *qq;
#pragma unroll
        for (int k = 0; k < 3; ++k) {
            pe[k] = fmaf(ALPHA[k], xv - pe[k], pe[k]);
            te[k] = fmaf(ALPHA[k], yv - te[k], te[k]);
        }
    }

    // Accumulation. sign(pe_t - pe_{t-1}) == sign(x_t - pe_{t-1}) since
    // alpha > 0, so the mismatch test is dx*dy < 0 on the FMA operands.
    const int tbeg = (c == 0) ? 1 : cs;
    const int tend = cs + CHUNK;
#pragma unroll 8
    for (int t = tbeg; t < tend; ++t, pp += Dn, qq += Dn) {
        float xv = *pp;
        float yv = *qq;
#pragma unroll
        for (int k = 0; k < 3; ++k) {
            float dx = xv - pe[k];
            float dy = yv - te[k];
            pe[k] = fmaf(ALPHA[k], dx, pe[k]);
            te[k] = fmaf(ALPHA[k], dy, te[k]);
            float e = pe[k] - te[k];
            if (dx * dy < 0.0f) acc[k] = fmaf(e, e, acc[k]);
        }
    }

    // Per-warp deterministic reduction -> one partial per warp.
    float local = 0.5f * acc[0] + 0.3f * acc[1] + 0.2f * acc[2];
#pragma unroll
    for (int off = 16; off > 0; off >>= 1)
        local += __shfl_down_sync(0xffffffffu, local, off);
    if (lane == 0) g_partial[gw] = local;

    // ---- Last-block-done final reduction (deterministic fixed-order sum) ----
    __syncthreads();
    __shared__ unsigned int s_last;
    if (threadIdx.x == 0) {
        __threadfence();
        s_last = (atomicAdd(&g_done, 1u) == (unsigned)(NBLK - 1));
    }
    __syncthreads();
    if (!s_last) return;

    __threadfence();  // order reads of g_partial after all producers' fences
    __shared__ float s[TPB];
    volatile float* vp = g_partial;
    float sum = 0.0f;
#pragma unroll
    for (int j = 0; j < NWARPS / TPB; ++j)          // 8 fixed-order adds/thread
        sum += vp[threadIdx.x * (NWARPS / TPB) + j];
    s[threadIdx.x] = sum;
    __syncthreads();
#pragma unroll
    for (int off = TPB / 2; off >= 32; off >>= 1) {
        if (threadIdx.x < off) s[threadIdx.x] += s[threadIdx.x + off];
        __syncthreads();
    }
    if (threadIdx.x < 32) {
        float v = s[threadIdx.x];
#pragma unroll
        for (int off = 16; off > 0; off >>= 1)
            v += __shfl_down_sync(0xffffffffu, v, off);
        if (threadIdx.x == 0) {
            out[0] = v * (1.0f / (8191.0f * 2048.0f));  // mean over (T-1), then B*D
            g_done = 0;  // reset for next (graph-replayed) launch
        }
    }
}

extern "C" void kernel_launch(void* const* d_in, const int* in_sizes, int n_in,
                              void* d_out, int out_size)
{
    const float* pred = (const float*)d_in[0];
    const float* tgt  = (const float*)d_in[1];
    msl_fused<<<NBLK, TPB>>>(pred, tgt, (float*)d_out);
}

// round 5
// speedup vs baseline: 2.1292x; 2.1292x over previous
#include <cuda_runtime.h>

// MultiScaleTrendDirectionLoss — fused EMA + sign-mismatch masked MSE.
// pred, target: [32, 8192, 64] fp32. Output: scalar fp32.
//
// R3: CHUNK=128/HALO=97 -> 4096 warps (~28/SM, single wave of 1024 blocks);
// explicit batch-of-4 register prefetch to force MLP=8 per warp (R2's regs=31
// showed ptxas had serialized the loads -> latency-bound at 1.9 TB/s).

#define Bn 32
#define Tn 8192
#define Dn 64
#define CHUNK 128
#define HALO 97                     // warm iters = 96 (multiple of 4)
#define NCHUNK (Tn / CHUNK)         // 64
#define NROWS (Bn * NCHUNK)         // 2048
#define NWARPS (NROWS * 2)          // 4096 (two d-halves per row)
#define TPB 128
#define WPB (TPB / 32)              // 4
#define NBLK (NWARPS / WPB)         // 1024

__device__ float g_partial[NWARPS];
__device__ unsigned int g_done = 0;

__global__ __launch_bounds__(TPB, 8) void msl_fused(const float* __restrict__ pred,
                                                    const float* __restrict__ tgt,
                                                    float* __restrict__ out)
{
    const int lane = threadIdx.x & 31;
    const int wid  = threadIdx.x >> 5;
    const int gw   = blockIdx.x * WPB + wid;   // global warp id
    const int row  = gw >> 1;                  // (b, chunk)
    const int half = gw & 1;
    const int b  = row >> 6;                   // row / NCHUNK
    const int c  = row & 63;                   // row % NCHUNK
    const int cs = c * CHUNK;
    const int t0 = (c == 0) ? 0 : (cs - HALO);
    const int d  = half * 32 + lane;

    const float* __restrict__ pp = pred + ((size_t)(b * Tn + t0)) * Dn + d;
    const float* __restrict__ qq = tgt  + ((size_t)(b * Tn + t0)) * Dn + d;

    const float ALPHA[3] = {0.1f, 0.3f, 0.5f};

    // Seed EMA state with element at t0 (exact for chunk 0; halo warm-up else —
    // (0.9)^96 ~ 4e-5 residual, far below the 1e-3 tolerance).
    float x0 = *pp;
    float y0 = *qq;
    float pe[3], te[3], acc[3];
#pragma unroll
    for (int k = 0; k < 3; ++k) { pe[k] = x0; te[k] = y0; acc[k] = 0.0f; }
    pp += Dn;
    qq += Dn;

    const int nwarm = (c == 0) ? 0 : (HALO - 1);   // 0 or 96
    const int nacc  = (c == 0) ? (CHUNK - 1) : CHUNK;

    // ---- Warm-up: batches of 4, loads hoisted into register arrays (MLP=8).
    for (int i = 0; i < nwarm; i += 4) {
        float xv[4], yv[4];
#pragma unroll
        for (int j = 0; j < 4; ++j) { xv[j] = pp[j * Dn]; yv[j] = qq[j * Dn]; }
        pp += 4 * Dn; qq += 4 * Dn;
#pragma unroll
        for (int j = 0; j < 4; ++j) {
#pragma unroll
            for (int k = 0; k < 3; ++k) {
                pe[k] = fmaf(ALPHA[k], xv[j] - pe[k], pe[k]);
                te[k] = fmaf(ALPHA[k], yv[j] - te[k], te[k]);
            }
        }
    }

    // ---- Accumulation. sign(pe_t - pe_{t-1}) == sign(x_t - pe_{t-1}) since
    // alpha > 0, so the mismatch test is dx*dy < 0 on the FMA operands.
    const int nacc4 = nacc & ~3;
    int i = 0;
    for (; i < nacc4; i += 4) {
        float xv[4], yv[4];
#pragma unroll
        for (int j = 0; j < 4; ++j) { xv[j] = pp[j * Dn]; yv[j] = qq[j * Dn]; }
        pp += 4 * Dn; qq += 4 * Dn;
#pragma unroll
        for (int j = 0; j < 4; ++j) {
#pragma unroll
            for (int k = 0; k < 3; ++k) {
                float dx = xv[j] - pe[k];
                float dy = yv[j] - te[k];
                pe[k] = fmaf(ALPHA[k], dx, pe[k]);
                te[k] = fmaf(ALPHA[k], dy, te[k]);
                float e = pe[k] - te[k];
                if (dx * dy < 0.0f) acc[k] = fmaf(e, e, acc[k]);
            }
        }
    }
    for (; i < nacc; ++i) {                      // remainder (3 iters, chunk 0 only)
        float xv = *pp, yv = *qq;
        pp += Dn; qq += Dn;
#pragma unroll
        for (int k = 0; k < 3; ++k) {
            float dx = xv - pe[k];
            float dy = yv - te[k];
            pe[k] = fmaf(ALPHA[k], dx, pe[k]);
            te[k] = fmaf(ALPHA[k], dy, te[k]);
            float e = pe[k] - te[k];
            if (dx * dy < 0.0f) acc[k] = fmaf(e, e, acc[k]);
        }
    }

    // Per-warp deterministic reduction -> one partial per warp.
    float local = 0.5f * acc[0] + 0.3f * acc[1] + 0.2f * acc[2];
#pragma unroll
    for (int off = 16; off > 0; off >>= 1)
        local += __shfl_down_sync(0xffffffffu, local, off);
    if (lane == 0) g_partial[gw] = local;

    // ---- Last-block-done final reduction (deterministic fixed-order sum) ----
    __syncthreads();
    __shared__ unsigned int s_last;
    if (threadIdx.x == 0) {
        __threadfence();
        s_last = (atomicAdd(&g_done, 1u) == (unsigned)(NBLK - 1));
    }
    __syncthreads();
    if (!s_last) return;

    __threadfence();
    __shared__ float s[TPB];
    volatile float* vp = g_partial;
    float sum = 0.0f;
#pragma unroll
    for (int j = 0; j < NWARPS / TPB; ++j)       // 32 fixed-order adds/thread
        sum += vp[threadIdx.x * (NWARPS / TPB) + j];
    s[threadIdx.x] = sum;
    __syncthreads();
#pragma unroll
    for (int off = TPB / 2; off >= 32; off >>= 1) {
        if (threadIdx.x < off) s[threadIdx.x] += s[threadIdx.x + off];
        __syncthreads();
    }
    if (threadIdx.x < 32) {
        float v = s[threadIdx.x];
#pragma unroll
        for (int off = 16; off > 0; off >>= 1)
            v += __shfl_down_sync(0xffffffffu, v, off);
        if (threadIdx.x == 0) {
            out[0] = v * (1.0f / (8191.0f * 2048.0f));  // mean over (T-1), then B*D
            g_done = 0;  // reset for next graph replay
        }
    }
}

extern "C" void kernel_launch(void* const* d_in, const int* in_sizes, int n_in,
                              void* d_out, int out_size)
{
    const float* pred = (const float*)d_in[0];
    const float* tgt  = (const float*)d_in[1];
    msl_fused<<<NBLK, TPB>>>(pred, tgt, (float*)d_out);
}